// round 16
// baseline (speedup 1.0000x reference)
#include <cuda_runtime.h>
#include <cuda_bf16.h>
#include <cstdint>

// Problem constants
#define Bsz   128
#define Gsz   100
#define Lz    16
#define HL    512
#define Dd    64
#define OUTSZ 8450   // 64+1 + 4096+64 + 4096+64 + 64+1

typedef unsigned long long ULL;

// Scratch (device globals). Hidden activations transposed [k][m].
__device__ __align__(16) float g_h0t[HL * Bsz];
__device__ __align__(16) float g_h1t[HL * Bsz];
__device__ __align__(16) float g_h2t[HL * Bsz];
__device__ __align__(16) float g_wab[Bsz * OUTSZ];
// Presplit A tile images: 8 chunks x 3 passes x (64 x 136) halfs = 417 KB
__device__ __align__(16) uint16_t g_asp[8 * 3 * 64 * 136];

__device__ __forceinline__ float leaky(float v) { return v > 0.f ? v : 0.01f * v; }

// ---- packed fp32x2 helpers ----
__device__ __forceinline__ ULL pack2(float lo, float hi) {
    ULL r; asm("mov.b64 %0, {%1, %2};" : "=l"(r) : "f"(lo), "f"(hi)); return r;
}
__device__ __forceinline__ ULL dup2(float x) {
    ULL r; asm("mov.b64 %0, {%1, %1};" : "=l"(r) : "f"(x)); return r;
}
__device__ __forceinline__ void unpack2(ULL v, float& lo, float& hi) {
    asm("mov.b64 {%0, %1}, %2;" : "=f"(lo), "=f"(hi) : "l"(v));
}
__device__ __forceinline__ void ffma2(ULL& acc, ULL a, ULL b) {
    asm("fma.rn.f32x2 %0, %1, %2, %0;" : "+l"(acc) : "l"(a), "l"(b));
}

// ---- warp MMA primitives (sm_80 baseline PTX: legal at target sm_100) ----
__device__ __forceinline__ uint32_t smem_u32(const void* p) {
    uint32_t a;
    asm("{ .reg .u64 t; cvta.to.shared.u64 t, %1; cvt.u32.u64 %0, t; }"
        : "=r"(a) : "l"(p));
    return a;
}
__device__ __forceinline__ void ldm4(uint32_t* a, uint32_t addr) {
    asm volatile("ldmatrix.sync.aligned.m8n8.x4.trans.shared.b16 {%0,%1,%2,%3}, [%4];"
                 : "=r"(a[0]), "=r"(a[1]), "=r"(a[2]), "=r"(a[3]) : "r"(addr));
}
__device__ __forceinline__ void mma16816(float* c, const uint32_t* a,
                                         uint32_t b0, uint32_t b1) {
    asm volatile("mma.sync.aligned.m16n8k16.row.col.f32.bf16.bf16.f32 "
                 "{%0,%1,%2,%3}, {%4,%5,%6,%7}, {%8,%9}, {%0,%1,%2,%3};"
                 : "+f"(c[0]), "+f"(c[1]), "+f"(c[2]), "+f"(c[3])
                 : "r"(a[0]), "r"(a[1]), "r"(a[2]), "r"(a[3]), "r"(b0), "r"(b1));
}

// Truncation-based 3-term split of TWO floats -> 3 packed bf16x2 words.
__device__ __forceinline__ void split3t2(float x0, float x1,
                                         uint32_t& hp, uint32_t& mp, uint32_t& lp) {
    uint32_t u0 = __float_as_uint(x0), u1 = __float_as_uint(x1);
    hp = __byte_perm(u0, u1, 0x7632);
    float r0 = x0 - __uint_as_float(u0 & 0xffff0000u);
    float r1 = x1 - __uint_as_float(u1 & 0xffff0000u);
    uint32_t v0 = __float_as_uint(r0), v1 = __float_as_uint(r1);
    mp = __byte_perm(v0, v1, 0x7632);
    float s0 = r0 - __uint_as_float(v0 & 0xffff0000u);
    float s1 = r1 - __uint_as_float(v1 & 0xffff0000u);
    asm("cvt.rn.bf16x2.f32 %0, %1, %2;" : "=r"(lp) : "f"(s1), "f"(s0));
}

// ---------------------------------------------------------------------------
// Kernel 1: h0t[j][b] = leaky(z[b] . hW0[:,j] + hb0[j])
// ---------------------------------------------------------------------------
__global__ void k_h0(const float* __restrict__ z, const float* __restrict__ hW0,
                     const float* __restrict__ hb0) {
    __shared__ float zs[Lz];
    int b = blockIdx.x;
    int j = threadIdx.x;
    if (j < Lz) zs[j] = z[b * Lz + j];
    __syncthreads();
    float acc = hb0[j];
#pragma unroll
    for (int i = 0; i < Lz; i++) acc = fmaf(zs[i], hW0[i * HL + j], acc);
    g_h0t[j * Bsz + b] = leaky(acc);
}

// ---------------------------------------------------------------------------
// Hidden GEMM (pipelined, trans-A, trans-out), BN=4 -> grid 128:
//   Ct[n][m] = leaky( sum_k At[k][m] * W[k][n] + bias[n] )
// ---------------------------------------------------------------------------
__global__ void __launch_bounds__(256, 1) hid_gemm(const float* __restrict__ At,
                                                   const float* __restrict__ W,
                                                   const float* __restrict__ bias,
                                                   float* __restrict__ Ct) {
    constexpr int BK = 64, BN = 4, S = 3, K = 512, NT = K / BK;
    constexpr int ASZ = BK * 128;
    constexpr int BSZ = BK * BN;
    extern __shared__ float sm[];
    float* As = sm;
    float* Bs = sm + S * ASZ;

    const int tid  = threadIdx.x;
    const int n0   = blockIdx.x * BN;
    const int tcol = tid & 3;
    const int trow = tid >> 2;       // 0..63
    const int m0   = trow * 2;

    auto load_tile = [&](int t, int s) {
        float* Ad = As + s * ASZ;
        const float* Ag = At + t * BK * 128;
#pragma unroll
        for (int u = 0; u < 8; u++) {
            int idx = tid + u * 256;
            int row = idx >> 5, col = (idx & 31) << 2;
            uint32_t d = (uint32_t)__cvta_generic_to_shared(Ad + row * 128 + col);
            asm volatile("cp.async.cg.shared.global [%0], [%1], 16;"
                         :: "r"(d), "l"(Ag + row * 128 + col));
        }
        if (tid < 64) {
            float* Bd = Bs + s * BSZ;
            uint32_t d = (uint32_t)__cvta_generic_to_shared(Bd + tid * BN);
            asm volatile("cp.async.ca.shared.global [%0], [%1], 16;"
                         :: "r"(d), "l"(W + (size_t)(t * BK + tid) * HL + n0));
        }
        asm volatile("cp.async.commit_group;");
    };

    ULL acc = 0;
    load_tile(0, 0);
    load_tile(1, 1);

    for (int t = 0; t < NT; t++) {
        if (t + 1 < NT) asm volatile("cp.async.wait_group 1;");
        else            asm volatile("cp.async.wait_group 0;");
        __syncthreads();
        if (t + 2 < NT) load_tile(t + 2, (t + 2) % S);

        const float* As_ = As + (t % S) * ASZ;
        const float* Bs_ = Bs + (t % S) * BSZ;
#pragma unroll
        for (int kk = 0; kk < BK; kk++) {
            ULL a = *reinterpret_cast<const ULL*>(As_ + kk * 128 + m0);
            ULL bd = dup2(Bs_[kk * BN + tcol]);
            ffma2(acc, a, bd);
        }
        __syncthreads();
    }

    float v0, v1;
    unpack2(acc, v0, v1);
    int gn = n0 + tcol;
    float bb = bias[gn];
    float2 out = make_float2(leaky(v0 + bb), leaky(v1 + bb));
    *reinterpret_cast<float2*>(Ct + gn * Bsz + m0) = out;
}
#define HID_SMEM_BYTES (3 * (64 * 128 + 64 * 4) * 4)   // ~99 KB

// ---------------------------------------------------------------------------
// prep_a: split h2t chunk (64x128 fp32) into 3 bf16 tile images per chunk,
// in EXACTLY the smem layout wab_mma wants ([k][m], row stride 136 halfs).
// Grid 8 (one block per 64-k chunk), 256 threads.
// ---------------------------------------------------------------------------
__global__ void prep_a() {
    const int ch  = blockIdx.x;
    const int tid = threadIdx.x;
    const float* At = g_h2t + ch * 64 * 128;
    uint16_t* dst = g_asp + ch * (3 * 64 * 136);    // 26112 halfs per chunk
#pragma unroll
    for (int u = 0; u < 8; u++) {
        int slot = tid + u * 256;                   // 2048 float4 slots
        int k = slot >> 5, m4 = (slot & 31) << 2;
        float4 v = *reinterpret_cast<const float4*>(At + k * 128 + m4);
        uint32_t h0, m0_, l0, h1, m1_, l1;
        split3t2(v.x, v.y, h0, m0_, l0);
        split3t2(v.z, v.w, h1, m1_, l1);
        int off = k * 136 + m4;                     // halfs within an image
        *reinterpret_cast<uint2*>(dst + 0 * 8704 + off) = make_uint2(h0, h1);
        *reinterpret_cast<uint2*>(dst + 1 * 8704 + off) = make_uint2(m0_, m1_);
        *reinterpret_cast<uint2*>(dst + 2 * 8704 + off) = make_uint2(l0, l1);
    }
}

// ---------------------------------------------------------------------------
// wab GEMM, mma.sync bf16, 512 threads:
//   C(128, 8450) = A^T(128,512) @ W(512,8450) + bias
// A arrives PRESPLIT (flat cp.async of g_asp images, double-buffered).
// B: raw fp32 staged (double-buffered) + in-kernel truncation split
// into single-buffered bf16 tiles. 6-pass 3-term split MMA (R14 inner loop).
// smem: A images 2x52224 + raw B 2x16384 + B tiles 27648 = 164864 B.
// ---------------------------------------------------------------------------
#define WA_STR  136
#define WB_STR  72
#define WA_TILE 17408          // bytes per A image
#define WB_TILE 9216           // bytes per B tile
#define A_IMGS  52224          // 3 * WA_TILE
#define ABUF(b) ((b) * A_IMGS)                 // 0 / 52224
#define RAWB(b) (104448 + (b) * 16384)         // raw B fp32
#define WB_BASE 137216
#define WB_OFF(p) (WB_BASE + (p) * WB_TILE)
#define WMS_SMEM (WB_BASE + 3 * WB_TILE)       // 164864 B

__global__ void __launch_bounds__(512, 1) wab_mma(const float* __restrict__ W,
                                                  const float* __restrict__ bias,
                                                  float* __restrict__ C) {
    constexpr int N = OUTSZ, NCH = 8;
    extern __shared__ char smc[];
    const int tid  = threadIdx.x;
    const int wid  = tid >> 5;
    const int lane = tid & 31;
    const int n0   = blockIdx.x * 64;
    const uint32_t sb = smem_u32(smc);

    auto load_tiles = [&](int c, int buf) {
        // A: presplit images, 52224 B = 3264 x 16B chunks
        const char* srcA = reinterpret_cast<const char*>(g_asp) + c * A_IMGS;
#pragma unroll
        for (int u = 0; u < 7; u++) {
            int idx = tid + u * 512;
            if (idx < 3264) {
                uint32_t d = sb + ABUF(buf) + idx * 16;
                asm volatile("cp.async.cg.shared.global [%0], [%1], 16;"
                             :: "r"(d), "l"(srcA + idx * 16));
            }
        }
        // raw B: 64x64 fp32 = 2048 x 8B chunks (exactly 4 x 512)
        const int k0 = c * 64;
#pragma unroll
        for (int u = 0; u < 4; u++) {
            int idx = tid + u * 512;
            int k = idx >> 5, n2 = (idx & 31) << 1;
            int gn = n0 + n2;
            uint32_t d = sb + RAWB(buf) + (k * 64 + n2) * 4;
            const float* src = W + (size_t)(k0 + k) * N + (gn + 1 < N ? gn : 0);
            int bytes = (gn + 1 < N) ? 8 : 0;
            asm volatile("cp.async.ca.shared.global [%0], [%1], 8, %2;"
                         :: "r"(d), "l"(src), "r"(bytes));
        }
        asm volatile("cp.async.commit_group;");
    };

    const int m0    = (wid & 7) * 16;
    const int nbase = (wid >> 3) * 4;
    float acc[4][4];
#pragma unroll
    for (int i = 0; i < 4; i++)
#pragma unroll
        for (int j = 0; j < 4; j++) acc[i][j] = 0.f;

    // per-lane ldmatrix offsets (bytes, within a tile) — R14 proven
    const int g  = lane >> 3, l = lane & 7;
    const uint32_t a_lane = (uint32_t)((((g >> 1) & 1) * 8 + l) * (WA_STR * 2)
                                       + (m0 + (g & 1) * 8) * 2);
    const int lb = lane & 15;
    const uint32_t b_lane = (uint32_t)((((lb >> 3) * 8) + (lb & 7)) * (WB_STR * 2)
                                       + ((lane >> 4) << 4));

    load_tiles(0, 0);

    for (int c = 0; c < NCH; c++) {
        const int buf = c & 1;
        asm volatile("cp.async.wait_group 0;");
        __syncthreads();

        // ---- split B raw -> bf16 tiles (2048 float2 slots = 4 x 512) ----
        const float* rawB = reinterpret_cast<const float*>(smc + RAWB(buf));
#pragma unroll
        for (int u = 0; u < 4; u++) {
            int slot = tid + u * 512;
            int k = slot >> 5, n2 = (slot & 31) << 1;
            float2 wv = *reinterpret_cast<const float2*>(rawB + k * 64 + n2);
            uint32_t hp, mp, lp;
            split3t2(wv.x, wv.y, hp, mp, lp);
            uint32_t base = (uint32_t)(k * (WB_STR * 2) + n2 * 2);
            *reinterpret_cast<uint32_t*>(smc + WB_OFF(0) + base) = hp;
            *reinterpret_cast<uint32_t*>(smc + WB_OFF(1) + base) = mp;
            *reinterpret_cast<uint32_t*>(smc + WB_OFF(2) + base) = lp;
        }
        __syncthreads();

        // ---- prefetch next chunk (A images + raw B), hidden under MMA ----
        if (c + 1 < NCH) load_tiles(c + 1, buf ^ 1);

        // ---- MMA: 4 k16-steps x 2 tile-pairs x 6 split passes ----
        const uint32_t abase = sb + ABUF(buf);
#pragma unroll
        for (int ks = 0; ks < 4; ks++) {
            uint32_t ao = a_lane + (uint32_t)(ks * 16 * WA_STR * 2);
            uint32_t Ah[4], Am[4], Al[4];
            ldm4(Ah, abase + 0 * WA_TILE + ao);
            ldm4(Am, abase + 1 * WA_TILE + ao);
            ldm4(Al, abase + 2 * WA_TILE + ao);
            uint32_t bo = b_lane + (uint32_t)(ks * 16 * WB_STR * 2);
#pragma unroll
            for (int jp = 0; jp < 4; jp += 2) {
                uint32_t off = bo + (uint32_t)((nbase + jp) * 16);
                uint32_t Bh[4], Bm[4], Bl[4];
                ldm4(Bh, sb + WB_OFF(0) + off);
                ldm4(Bm, sb + WB_OFF(1) + off);
                ldm4(Bl, sb + WB_OFF(2) + off);
                mma16816(acc[jp],     Ah, Bh[0], Bh[1]);
                mma16816(acc[jp + 1], Ah, Bh[2], Bh[3]);
                mma16816(acc[jp],     Ah, Bm[0], Bm[1]);
                mma16816(acc[jp + 1], Ah, Bm[2], Bm[3]);
                mma16816(acc[jp],     Am, Bh[0], Bh[1]);
                mma16816(acc[jp + 1], Am, Bh[2], Bh[3]);
                mma16816(acc[jp],     Am, Bm[0], Bm[1]);
                mma16816(acc[jp + 1], Am, Bm[2], Bm[3]);
                mma16816(acc[jp],     Ah, Bl[0], Bl[1]);
                mma16816(acc[jp + 1], Ah, Bl[2], Bl[3]);
                mma16816(acc[jp],     Al, Bh[0], Bh[1]);
                mma16816(acc[jp + 1], Al, Bh[2], Bh[3]);
            }
        }
        __syncthreads();   // B tiles + A buf free before next overwrite
    }

    // ---- Epilogue: fragment layout -> C + bias ----
    const int r0 = m0 + (lane >> 2);
    const int r1 = r0 + 8;
    const int cb0 = (lane & 3) * 2;
#pragma unroll
    for (int j = 0; j < 4; j++) {
        int gc = n0 + (nbase + j) * 8 + cb0;
        if (gc + 1 < N) {
            float b0v = bias[gc], b1v = bias[gc + 1];
            *reinterpret_cast<float2*>(C + (size_t)r0 * N + gc) =
                make_float2(acc[j][0] + b0v, acc[j][1] + b1v);
            *reinterpret_cast<float2*>(C + (size_t)r1 * N + gc) =
                make_float2(acc[j][2] + b0v, acc[j][3] + b1v);
        } else if (gc < N) {
            float b0v = bias[gc];
            C[(size_t)r0 * N + gc] = acc[j][0] + b0v;
            C[(size_t)r1 * N + gc] = acc[j][2] + b0v;
        }
    }
}

// ---------------------------------------------------------------------------
// Decoder (R14 known-good): one block per b, one thread per g.
// ---------------------------------------------------------------------------
#define SW1 0        // 4096
#define SW2 4096     // 4096
#define SW0 8192     // 64
#define SW3 8256     // 64
#define SB1 8320     // 64
#define SB2 8384     // 64
#define SB0 8448
#define SB3 8449
#define SX  8452
#define XSTRIDE 65
#define DEC_SMEM_FLOATS (SX + 128 * XSTRIDE)
#define DEC_SMEM_BYTES  (DEC_SMEM_FLOATS * 4)

__device__ __forceinline__ void dec_layer(const float* __restrict__ s,
                                          float* __restrict__ xs,
                                          int wbase, int bbase) {
    ULL acc[32];
#pragma unroll
    for (int q = 0; q < 16; q++) {
        float4 bb = *reinterpret_cast<const float4*>(s + bbase + q * 4);
        acc[2 * q]     = pack2(bb.x, bb.y);
        acc[2 * q + 1] = pack2(bb.z, bb.w);
    }
#pragma unroll 4
    for (int i = 0; i < Dd; i++) {
        ULL vd = dup2(xs[i]);
        const ulonglong2* wr = reinterpret_cast<const ulonglong2*>(s + wbase + i * Dd);
#pragma unroll
        for (int q = 0; q < 16; q++) {
            ulonglong2 w2 = wr[q];
            ffma2(acc[2 * q],     vd, w2.x);
            ffma2(acc[2 * q + 1], vd, w2.y);
        }
    }
#pragma unroll
    for (int q = 0; q < 32; q++) {
        float lo, hi;
        unpack2(acc[q], lo, hi);
        xs[2 * q]     = __sinf(lo);
        xs[2 * q + 1] = __sinf(hi);
    }
}

__global__ void __launch_bounds__(128) decoder_kernel(const float* __restrict__ log_P,
                                                      float* __restrict__ out) {
    extern __shared__ float s[];
    const int b = blockIdx.x;
    const int tid = threadIdx.x;
    const float* gw = g_wab + (size_t)b * OUTSZ;

    for (int i = tid; i < 4096; i += 128) s[SW1 + i] = gw[65 + i];
    for (int i = tid; i < 4096; i += 128) s[SW2 + i] = gw[4225 + i];
    if (tid < 64) {
        s[SW0 + tid] = gw[tid];
        s[SW3 + tid] = gw[8385 + tid];
        s[SB1 + tid] = gw[4161 + tid];
        s[SB2 + tid] = gw[8321 + tid];
    }
    if (tid == 0) { s[SB0] = gw[64]; s[SB3] = gw[8449]; }
    __syncthreads();

    if (tid < Gsz) {
        float x = log_P[b * Gsz + tid] * (1.f / 3.f);
        float* xs = &s[SX + tid * XSTRIDE];
        float b0 = s[SB0];
#pragma unroll
        for (int j = 0; j < Dd; j++)
            xs[j] = __sinf(30.f * fmaf(x, s[SW0 + j], b0));

        dec_layer(s, xs, SW1, SB1);
        dec_layer(s, xs, SW2, SB2);

        float accf = s[SB3];
#pragma unroll
        for (int i = 0; i < Dd; i++) accf = fmaf(xs[i], s[SW3 + i], accf);
        out[b * Gsz + tid] = fmaf(accf, 500.f, 1500.f);
    }
}

// ---------------------------------------------------------------------------
// Launch
// ---------------------------------------------------------------------------
extern "C" void kernel_launch(void* const* d_in, const int* in_sizes, int n_in,
                              void* d_out, int out_size) {
    const float* z     = (const float*)d_in[0];
    const float* log_P = (const float*)d_in[1];
    const float* hW0   = (const float*)d_in[2];
    const float* hb0   = (const float*)d_in[3];
    const float* hW1   = (const float*)d_in[4];
    const float* hb1   = (const float*)d_in[5];
    const float* hW2   = (const float*)d_in[6];
    const float* hb2   = (const float*)d_in[7];
    const float* hWo   = (const float*)d_in[8];
    const float* hbo   = (const float*)d_in[9];
    float* out = (float*)d_out;

    float *h0tp, *h1tp, *h2tp, *wabp;
    cudaGetSymbolAddress((void**)&h0tp, g_h0t);
    cudaGetSymbolAddress((void**)&h1tp, g_h1t);
    cudaGetSymbolAddress((void**)&h2tp, g_h2t);
    cudaGetSymbolAddress((void**)&wabp, g_wab);

    cudaFuncSetAttribute(hid_gemm, cudaFuncAttributeMaxDynamicSharedMemorySize,
                         HID_SMEM_BYTES);
    cudaFuncSetAttribute(wab_mma, cudaFuncAttributeMaxDynamicSharedMemorySize,
                         WMS_SMEM);
    cudaFuncSetAttribute(decoder_kernel, cudaFuncAttributeMaxDynamicSharedMemorySize,
                         DEC_SMEM_BYTES);

    k_h0<<<Bsz, HL>>>(z, hW0, hb0);
    hid_gemm<<<HL / 4, 256, HID_SMEM_BYTES>>>(h0tp, hW1, hb1, h1tp);
    hid_gemm<<<HL / 4, 256, HID_SMEM_BYTES>>>(h1tp, hW2, hb2, h2tp);
    prep_a<<<8, 256>>>();
    wab_mma<<<(OUTSZ + 63) / 64, 512, WMS_SMEM>>>(hWo, hbo, wabp);
    decoder_kernel<<<Bsz, 128, DEC_SMEM_BYTES>>>(log_P, out);
}

// round 17
// speedup vs baseline: 1.0605x; 1.0605x over previous
#include <cuda_runtime.h>
#include <cuda_bf16.h>
#include <cstdint>

// Problem constants
#define Bsz   128
#define Gsz   100
#define Lz    16
#define HL    512
#define Dd    64
#define OUTSZ 8450   // 64+1 + 4096+64 + 4096+64 + 64+1

typedef unsigned long long ULL;

// Scratch (device globals). Hidden activations transposed [k][m].
__device__ __align__(16) float g_h0t[HL * Bsz];
__device__ __align__(16) float g_h1t[HL * Bsz];
__device__ __align__(16) float g_h2t[HL * Bsz];
__device__ __align__(16) float g_wab[Bsz * OUTSZ];
// Presplit A tile images: 8 chunks x 3 passes x (64 x 136) halfs = 417 KB
__device__ __align__(16) uint16_t g_asp[8 * 3 * 64 * 136];

__device__ __forceinline__ float leaky(float v) { return v > 0.f ? v : 0.01f * v; }

// ---- packed fp32x2 helpers ----
__device__ __forceinline__ ULL pack2(float lo, float hi) {
    ULL r; asm("mov.b64 %0, {%1, %2};" : "=l"(r) : "f"(lo), "f"(hi)); return r;
}
__device__ __forceinline__ ULL dup2(float x) {
    ULL r; asm("mov.b64 %0, {%1, %1};" : "=l"(r) : "f"(x)); return r;
}
__device__ __forceinline__ void unpack2(ULL v, float& lo, float& hi) {
    asm("mov.b64 {%0, %1}, %2;" : "=f"(lo), "=f"(hi) : "l"(v));
}
__device__ __forceinline__ void ffma2(ULL& acc, ULL a, ULL b) {
    asm("fma.rn.f32x2 %0, %1, %2, %0;" : "+l"(acc) : "l"(a), "l"(b));
}

// ---- warp MMA primitives (sm_80 baseline PTX: legal at target sm_100) ----
__device__ __forceinline__ uint32_t smem_u32(const void* p) {
    uint32_t a;
    asm("{ .reg .u64 t; cvta.to.shared.u64 t, %1; cvt.u32.u64 %0, t; }"
        : "=r"(a) : "l"(p));
    return a;
}
__device__ __forceinline__ void ldm4(uint32_t* a, uint32_t addr) {
    asm volatile("ldmatrix.sync.aligned.m8n8.x4.trans.shared.b16 {%0,%1,%2,%3}, [%4];"
                 : "=r"(a[0]), "=r"(a[1]), "=r"(a[2]), "=r"(a[3]) : "r"(addr));
}
__device__ __forceinline__ void mma16816(float* c, const uint32_t* a,
                                         uint32_t b0, uint32_t b1) {
    asm volatile("mma.sync.aligned.m16n8k16.row.col.f32.bf16.bf16.f32 "
                 "{%0,%1,%2,%3}, {%4,%5,%6,%7}, {%8,%9}, {%0,%1,%2,%3};"
                 : "+f"(c[0]), "+f"(c[1]), "+f"(c[2]), "+f"(c[3])
                 : "r"(a[0]), "r"(a[1]), "r"(a[2]), "r"(a[3]), "r"(b0), "r"(b1));
}

// Truncation-based 3-term split of TWO floats -> 3 packed bf16x2 words.
__device__ __forceinline__ void split3t2(float x0, float x1,
                                         uint32_t& hp, uint32_t& mp, uint32_t& lp) {
    uint32_t u0 = __float_as_uint(x0), u1 = __float_as_uint(x1);
    hp = __byte_perm(u0, u1, 0x7632);
    float r0 = x0 - __uint_as_float(u0 & 0xffff0000u);
    float r1 = x1 - __uint_as_float(u1 & 0xffff0000u);
    uint32_t v0 = __float_as_uint(r0), v1 = __float_as_uint(r1);
    mp = __byte_perm(v0, v1, 0x7632);
    float s0 = r0 - __uint_as_float(v0 & 0xffff0000u);
    float s1 = r1 - __uint_as_float(v1 & 0xffff0000u);
    asm("cvt.rn.bf16x2.f32 %0, %1, %2;" : "=r"(lp) : "f"(s1), "f"(s0));
}

// ---------------------------------------------------------------------------
// Kernel 1: h0t[j][b] = leaky(z[b] . hW0[:,j] + hb0[j])
// ---------------------------------------------------------------------------
__global__ void k_h0(const float* __restrict__ z, const float* __restrict__ hW0,
                     const float* __restrict__ hb0) {
    __shared__ float zs[Lz];
    int b = blockIdx.x;
    int j = threadIdx.x;
    if (j < Lz) zs[j] = z[b * Lz + j];
    __syncthreads();
    float acc = hb0[j];
#pragma unroll
    for (int i = 0; i < Lz; i++) acc = fmaf(zs[i], hW0[i * HL + j], acc);
    g_h0t[j * Bsz + b] = leaky(acc);
}

// ---------------------------------------------------------------------------
// Hidden GEMM (pipelined, trans-A, trans-out), BN=4 -> grid 128:
//   Ct[n][m] = leaky( sum_k At[k][m] * W[k][n] + bias[n] )
// SPLIT variant (2nd layer): instead of storing Ct, store the 3-term bf16
// split of the activated outputs directly into g_asp (wab's A images).
// ---------------------------------------------------------------------------
template <bool SPLIT>
__global__ void __launch_bounds__(256, 1) hid_gemm(const float* __restrict__ At,
                                                   const float* __restrict__ W,
                                                   const float* __restrict__ bias,
                                                   float* __restrict__ Ct) {
    constexpr int BK = 64, BN = 4, S = 3, K = 512, NT = K / BK;
    constexpr int ASZ = BK * 128;
    constexpr int BSZ = BK * BN;
    extern __shared__ float sm[];
    float* As = sm;
    float* Bs = sm + S * ASZ;

    const int tid  = threadIdx.x;
    const int n0   = blockIdx.x * BN;
    const int tcol = tid & 3;
    const int trow = tid >> 2;       // 0..63
    const int m0   = trow * 2;

    auto load_tile = [&](int t, int s) {
        float* Ad = As + s * ASZ;
        const float* Ag = At + t * BK * 128;
#pragma unroll
        for (int u = 0; u < 8; u++) {
            int idx = tid + u * 256;
            int row = idx >> 5, col = (idx & 31) << 2;
            uint32_t d = (uint32_t)__cvta_generic_to_shared(Ad + row * 128 + col);
            asm volatile("cp.async.cg.shared.global [%0], [%1], 16;"
                         :: "r"(d), "l"(Ag + row * 128 + col));
        }
        if (tid < 64) {
            float* Bd = Bs + s * BSZ;
            uint32_t d = (uint32_t)__cvta_generic_to_shared(Bd + tid * BN);
            asm volatile("cp.async.ca.shared.global [%0], [%1], 16;"
                         :: "r"(d), "l"(W + (size_t)(t * BK + tid) * HL + n0));
        }
        asm volatile("cp.async.commit_group;");
    };

    ULL acc = 0;
    load_tile(0, 0);
    load_tile(1, 1);

    for (int t = 0; t < NT; t++) {
        if (t + 1 < NT) asm volatile("cp.async.wait_group 1;");
        else            asm volatile("cp.async.wait_group 0;");
        __syncthreads();
        if (t + 2 < NT) load_tile(t + 2, (t + 2) % S);

        const float* As_ = As + (t % S) * ASZ;
        const float* Bs_ = Bs + (t % S) * BSZ;
#pragma unroll
        for (int kk = 0; kk < BK; kk++) {
            ULL a = *reinterpret_cast<const ULL*>(As_ + kk * 128 + m0);
            ULL bd = dup2(Bs_[kk * BN + tcol]);
            ffma2(acc, a, bd);
        }
        __syncthreads();
    }

    float v0, v1;
    unpack2(acc, v0, v1);
    int gn = n0 + tcol;
    float bb = bias[gn];
    v0 = leaky(v0 + bb);
    v1 = leaky(v1 + bb);
    if (SPLIT) {
        // gn is wab's k index; write the 3 bf16 images at chunk gn>>6, row gn&63
        uint32_t hp, mp, lp;
        split3t2(v0, v1, hp, mp, lp);
        uint16_t* dst = g_asp + (gn >> 6) * 26112 + (gn & 63) * 136 + m0;
        *reinterpret_cast<uint32_t*>(dst + 0 * 8704) = hp;
        *reinterpret_cast<uint32_t*>(dst + 1 * 8704) = mp;
        *reinterpret_cast<uint32_t*>(dst + 2 * 8704) = lp;
    } else {
        *reinterpret_cast<float2*>(Ct + gn * Bsz + m0) = make_float2(v0, v1);
    }
}
#define HID_SMEM_BYTES (3 * (64 * 128 + 64 * 4) * 4)   // ~99 KB

// ---------------------------------------------------------------------------
// wab GEMM, mma.sync bf16, 512 threads:
//   C(128, 8450) = A^T(128,512) @ W(512,8450) + bias
// A arrives PRESPLIT (flat cp.async of g_asp images, double-buffered).
// B: raw fp32 staged (double-buffered) + in-kernel truncation split
// into single-buffered bf16 tiles. 6-pass 3-term split MMA.
// smem: A images 2x52224 + raw B 2x16384 + B tiles 27648 = 164864 B.
// ---------------------------------------------------------------------------
#define WA_STR  136
#define WB_STR  72
#define WA_TILE 17408          // bytes per A image
#define WB_TILE 9216           // bytes per B tile
#define A_IMGS  52224          // 3 * WA_TILE
#define ABUF(b) ((b) * A_IMGS)                 // 0 / 52224
#define RAWB(b) (104448 + (b) * 16384)         // raw B fp32
#define WB_BASE 137216
#define WB_OFF(p) (WB_BASE + (p) * WB_TILE)
#define WMS_SMEM (WB_BASE + 3 * WB_TILE)       // 164864 B

__global__ void __launch_bounds__(512, 1) wab_mma(const float* __restrict__ W,
                                                  const float* __restrict__ bias,
                                                  float* __restrict__ C) {
    constexpr int N = OUTSZ, NCH = 8;
    extern __shared__ char smc[];
    const int tid  = threadIdx.x;
    const int wid  = tid >> 5;
    const int lane = tid & 31;
    const int n0   = blockIdx.x * 64;
    const uint32_t sb = smem_u32(smc);

    auto load_tiles = [&](int c, int buf) {
        // A: presplit images, 52224 B = 3264 x 16B chunks
        const char* srcA = reinterpret_cast<const char*>(g_asp) + c * A_IMGS;
#pragma unroll
        for (int u = 0; u < 7; u++) {
            int idx = tid + u * 512;
            if (idx < 3264) {
                uint32_t d = sb + ABUF(buf) + idx * 16;
                asm volatile("cp.async.cg.shared.global [%0], [%1], 16;"
                             :: "r"(d), "l"(srcA + idx * 16));
            }
        }
        // raw B: 64x64 fp32 = 2048 x 8B chunks (exactly 4 x 512)
        const int k0 = c * 64;
#pragma unroll
        for (int u = 0; u < 4; u++) {
            int idx = tid + u * 512;
            int k = idx >> 5, n2 = (idx & 31) << 1;
            int gn = n0 + n2;
            uint32_t d = sb + RAWB(buf) + (k * 64 + n2) * 4;
            const float* src = W + (size_t)(k0 + k) * N + (gn + 1 < N ? gn : 0);
            int bytes = (gn + 1 < N) ? 8 : 0;
            asm volatile("cp.async.ca.shared.global [%0], [%1], 8, %2;"
                         :: "r"(d), "l"(src), "r"(bytes));
        }
        asm volatile("cp.async.commit_group;");
    };

    const int m0    = (wid & 7) * 16;
    const int nbase = (wid >> 3) * 4;
    float acc[4][4];
#pragma unroll
    for (int i = 0; i < 4; i++)
#pragma unroll
        for (int j = 0; j < 4; j++) acc[i][j] = 0.f;

    // per-lane ldmatrix offsets (bytes, within a tile)
    const int g  = lane >> 3, l = lane & 7;
    const uint32_t a_lane = (uint32_t)((((g >> 1) & 1) * 8 + l) * (WA_STR * 2)
                                       + (m0 + (g & 1) * 8) * 2);
    const int lb = lane & 15;
    const uint32_t b_lane = (uint32_t)((((lb >> 3) * 8) + (lb & 7)) * (WB_STR * 2)
                                       + ((lane >> 4) << 4));

    load_tiles(0, 0);

    for (int c = 0; c < NCH; c++) {
        const int buf = c & 1;
        asm volatile("cp.async.wait_group 0;");
        __syncthreads();

        // ---- split B raw -> bf16 tiles (2048 float2 slots = 4 x 512) ----
        const float* rawB = reinterpret_cast<const float*>(smc + RAWB(buf));
#pragma unroll
        for (int u = 0; u < 4; u++) {
            int slot = tid + u * 512;
            int k = slot >> 5, n2 = (slot & 31) << 1;
            float2 wv = *reinterpret_cast<const float2*>(rawB + k * 64 + n2);
            uint32_t hp, mp, lp;
            split3t2(wv.x, wv.y, hp, mp, lp);
            uint32_t base = (uint32_t)(k * (WB_STR * 2) + n2 * 2);
            *reinterpret_cast<uint32_t*>(smc + WB_OFF(0) + base) = hp;
            *reinterpret_cast<uint32_t*>(smc + WB_OFF(1) + base) = mp;
            *reinterpret_cast<uint32_t*>(smc + WB_OFF(2) + base) = lp;
        }
        __syncthreads();

        // ---- prefetch next chunk (A images + raw B), hidden under MMA ----
        if (c + 1 < NCH) load_tiles(c + 1, buf ^ 1);

        // ---- MMA: 4 k16-steps x 2 tile-pairs x 6 split passes ----
        const uint32_t abase = sb + ABUF(buf);
#pragma unroll
        for (int ks = 0; ks < 4; ks++) {
            uint32_t ao = a_lane + (uint32_t)(ks * 16 * WA_STR * 2);
            uint32_t Ah[4], Am[4], Al[4];
            ldm4(Ah, abase + 0 * WA_TILE + ao);
            ldm4(Am, abase + 1 * WA_TILE + ao);
            ldm4(Al, abase + 2 * WA_TILE + ao);
            uint32_t bo = b_lane + (uint32_t)(ks * 16 * WB_STR * 2);
#pragma unroll
            for (int jp = 0; jp < 4; jp += 2) {
                uint32_t off = bo + (uint32_t)((nbase + jp) * 16);
                uint32_t Bh[4], Bm[4], Bl[4];
                ldm4(Bh, sb + WB_OFF(0) + off);
                ldm4(Bm, sb + WB_OFF(1) + off);
                ldm4(Bl, sb + WB_OFF(2) + off);
                mma16816(acc[jp],     Ah, Bh[0], Bh[1]);
                mma16816(acc[jp + 1], Ah, Bh[2], Bh[3]);
                mma16816(acc[jp],     Ah, Bm[0], Bm[1]);
                mma16816(acc[jp + 1], Ah, Bm[2], Bm[3]);
                mma16816(acc[jp],     Am, Bh[0], Bh[1]);
                mma16816(acc[jp + 1], Am, Bh[2], Bh[3]);
                mma16816(acc[jp],     Am, Bm[0], Bm[1]);
                mma16816(acc[jp + 1], Am, Bm[2], Bm[3]);
                mma16816(acc[jp],     Ah, Bl[0], Bl[1]);
                mma16816(acc[jp + 1], Ah, Bl[2], Bl[3]);
                mma16816(acc[jp],     Al, Bh[0], Bh[1]);
                mma16816(acc[jp + 1], Al, Bh[2], Bh[3]);
            }
        }
        __syncthreads();   // B tiles + A buf free before next overwrite
    }

    // ---- Epilogue: fragment layout -> C + bias ----
    const int r0 = m0 + (lane >> 2);
    const int r1 = r0 + 8;
    const int cb0 = (lane & 3) * 2;
#pragma unroll
    for (int j = 0; j < 4; j++) {
        int gc = n0 + (nbase + j) * 8 + cb0;
        if (gc + 1 < N) {
            float b0v = bias[gc], b1v = bias[gc + 1];
            *reinterpret_cast<float2*>(C + (size_t)r0 * N + gc) =
                make_float2(acc[j][0] + b0v, acc[j][1] + b1v);
            *reinterpret_cast<float2*>(C + (size_t)r1 * N + gc) =
                make_float2(acc[j][2] + b0v, acc[j][3] + b1v);
        } else if (gc < N) {
            float b0v = bias[gc];
            C[(size_t)r0 * N + gc] = acc[j][0] + b0v;
            C[(size_t)r1 * N + gc] = acc[j][2] + b0v;
        }
    }
}

// ---------------------------------------------------------------------------
// Decoder (R14 known-good): one block per b, one thread per g.
// ---------------------------------------------------------------------------
#define SW1 0        // 4096
#define SW2 4096     // 4096
#define SW0 8192     // 64
#define SW3 8256     // 64
#define SB1 8320     // 64
#define SB2 8384     // 64
#define SB0 8448
#define SB3 8449
#define SX  8452
#define XSTRIDE 65
#define DEC_SMEM_FLOATS (SX + 128 * XSTRIDE)
#define DEC_SMEM_BYTES  (DEC_SMEM_FLOATS * 4)

__device__ __forceinline__ void dec_layer(const float* __restrict__ s,
                                          float* __restrict__ xs,
                                          int wbase, int bbase) {
    ULL acc[32];
#pragma unroll
    for (int q = 0; q < 16; q++) {
        float4 bb = *reinterpret_cast<const float4*>(s + bbase + q * 4);
        acc[2 * q]     = pack2(bb.x, bb.y);
        acc[2 * q + 1] = pack2(bb.z, bb.w);
    }
#pragma unroll 4
    for (int i = 0; i < Dd; i++) {
        ULL vd = dup2(xs[i]);
        const ulonglong2* wr = reinterpret_cast<const ulonglong2*>(s + wbase + i * Dd);
#pragma unroll
        for (int q = 0; q < 16; q++) {
            ulonglong2 w2 = wr[q];
            ffma2(acc[2 * q],     vd, w2.x);
            ffma2(acc[2 * q + 1], vd, w2.y);
        }
    }
#pragma unroll
    for (int q = 0; q < 32; q++) {
        float lo, hi;
        unpack2(acc[q], lo, hi);
        xs[2 * q]     = __sinf(lo);
        xs[2 * q + 1] = __sinf(hi);
    }
}

__global__ void __launch_bounds__(128) decoder_kernel(const float* __restrict__ log_P,
                                                      float* __restrict__ out) {
    extern __shared__ float s[];
    const int b = blockIdx.x;
    const int tid = threadIdx.x;
    const float* gw = g_wab + (size_t)b * OUTSZ;

    for (int i = tid; i < 4096; i += 128) s[SW1 + i] = gw[65 + i];
    for (int i = tid; i < 4096; i += 128) s[SW2 + i] = gw[4225 + i];
    if (tid < 64) {
        s[SW0 + tid] = gw[tid];
        s[SW3 + tid] = gw[8385 + tid];
        s[SB1 + tid] = gw[4161 + tid];
        s[SB2 + tid] = gw[8321 + tid];
    }
    if (tid == 0) { s[SB0] = gw[64]; s[SB3] = gw[8449]; }
    __syncthreads();

    if (tid < Gsz) {
        float x = log_P[b * Gsz + tid] * (1.f / 3.f);
        float* xs = &s[SX + tid * XSTRIDE];
        float b0 = s[SB0];
#pragma unroll
        for (int j = 0; j < Dd; j++)
            xs[j] = __sinf(30.f * fmaf(x, s[SW0 + j], b0));

        dec_layer(s, xs, SW1, SB1);
        dec_layer(s, xs, SW2, SB2);

        float accf = s[SB3];
#pragma unroll
        for (int i = 0; i < Dd; i++) accf = fmaf(xs[i], s[SW3 + i], accf);
        out[b * Gsz + tid] = fmaf(accf, 500.f, 1500.f);
    }
}

// ---------------------------------------------------------------------------
// Launch
// ---------------------------------------------------------------------------
extern "C" void kernel_launch(void* const* d_in, const int* in_sizes, int n_in,
                              void* d_out, int out_size) {
    const float* z     = (const float*)d_in[0];
    const float* log_P = (const float*)d_in[1];
    const float* hW0   = (const float*)d_in[2];
    const float* hb0   = (const float*)d_in[3];
    const float* hW1   = (const float*)d_in[4];
    const float* hb1   = (const float*)d_in[5];
    const float* hW2   = (const float*)d_in[6];
    const float* hb2   = (const float*)d_in[7];
    const float* hWo   = (const float*)d_in[8];
    const float* hbo   = (const float*)d_in[9];
    float* out = (float*)d_out;

    float *h0tp, *h1tp, *h2tp, *wabp;
    cudaGetSymbolAddress((void**)&h0tp, g_h0t);
    cudaGetSymbolAddress((void**)&h1tp, g_h1t);
    cudaGetSymbolAddress((void**)&h2tp, g_h2t);
    cudaGetSymbolAddress((void**)&wabp, g_wab);

    cudaFuncSetAttribute(hid_gemm<false>, cudaFuncAttributeMaxDynamicSharedMemorySize,
                         HID_SMEM_BYTES);
    cudaFuncSetAttribute(hid_gemm<true>, cudaFuncAttributeMaxDynamicSharedMemorySize,
                         HID_SMEM_BYTES);
    cudaFuncSetAttribute(wab_mma, cudaFuncAttributeMaxDynamicSharedMemorySize,
                         WMS_SMEM);
    cudaFuncSetAttribute(decoder_kernel, cudaFuncAttributeMaxDynamicSharedMemorySize,
                         DEC_SMEM_BYTES);

    k_h0<<<Bsz, HL>>>(z, hW0, hb0);
    hid_gemm<false><<<HL / 4, 256, HID_SMEM_BYTES>>>(h0tp, hW1, hb1, h1tp);
    hid_gemm<true ><<<HL / 4, 256, HID_SMEM_BYTES>>>(h1tp, hW2, hb2, h2tp);
    wab_mma<<<(OUTSZ + 63) / 64, 512, WMS_SMEM>>>(hWo, hbo, wabp);
    decoder_kernel<<<Bsz, 128, DEC_SMEM_BYTES>>>(log_P, out);
}